// round 15
// baseline (speedup 1.0000x reference)
#include <cuda_runtime.h>
#include <cuda_bf16.h>
#include <cstdint>

// ---------------------------------------------------------------------------
// Problem constants
// ---------------------------------------------------------------------------
#define S_DIM 128
#define Q_DIM 256
#define C_DIM 256
#define H_DIM 8
#define DH_DIM 32
#define M_ROWS (S_DIM * Q_DIM)        // 32768

// ---------------------------------------------------------------------------
// Scratch (static device globals; no allocation allowed). uint4 => 16B align.
// ---------------------------------------------------------------------------
#define XU4 (M_ROWS * 256 / 8)
#define WU4 (256 * 256 / 8)
__device__ uint4 g_qxh4[XU4],  g_qxl4[XU4];
__device__ uint4 g_kvxh4[XU4], g_kvxl4[XU4];
__device__ uint4 g_wqh4[WU4], g_wql4[WU4];
__device__ uint4 g_wkh4[WU4], g_wkl4[WU4];
__device__ uint4 g_wvh4[WU4], g_wvl4[WU4];
__device__ uint4 g_wgh4[WU4], g_wgl4[WU4];
__device__ uint4 g_woh4[WU4], g_wol4[WU4];
__device__ uint4 g_qhi4[XU4], g_qlo4[XU4];     // Q proj  [s][h][q][dh]
__device__ uint4 g_khi4[XU4], g_klo4[XU4];     // K proj  [s][h][q][dh]
__device__ uint4 g_vthi4[XU4], g_vtlo4[XU4];   // V proj  [s][h][dh][k]
__device__ uint4 g_obh4[XU4], g_obl4[XU4];     // attn out [m][tot]
__device__ float g_gbuf[M_ROWS * C_DIM];

// ---------------------------------------------------------------------------
// Helpers
// ---------------------------------------------------------------------------
__device__ __forceinline__ uint32_t smem_u32(const void* p) {
    uint32_t a;
    asm("{ .reg .u64 t; cvta.to.shared.u64 t, %1; cvt.u32.u64 %0, t; }"
        : "=r"(a) : "l"(p));
    return a;
}
__device__ __forceinline__ void cp16(uint32_t dst, const void* src) {
    asm volatile("cp.async.cg.shared.global [%0], [%1], 16;"
                 :: "r"(dst), "l"(src) : "memory");
}
__device__ __forceinline__ void cp_commit() {
    asm volatile("cp.async.commit_group;" ::: "memory");
}
template <int N>
__device__ __forceinline__ void cp_wait() {
    asm volatile("cp.async.wait_group %0;" :: "n"(N) : "memory");
}
__device__ __forceinline__ void ldsm_x4(uint32_t& r0, uint32_t& r1,
                                        uint32_t& r2, uint32_t& r3,
                                        uint32_t addr) {
    asm volatile("ldmatrix.sync.aligned.m8n8.x4.shared.b16 {%0,%1,%2,%3}, [%4];"
                 : "=r"(r0), "=r"(r1), "=r"(r2), "=r"(r3) : "r"(addr));
}
__device__ __forceinline__ void mma_bf16(float* d, const uint32_t* a,
                                         const uint32_t* b) {
    asm volatile(
        "mma.sync.aligned.m16n8k16.row.col.f32.bf16.bf16.f32 "
        "{%0,%1,%2,%3}, {%4,%5,%6,%7}, {%8,%9}, {%0,%1,%2,%3};"
        : "+f"(d[0]), "+f"(d[1]), "+f"(d[2]), "+f"(d[3])
        : "r"(a[0]), "r"(a[1]), "r"(a[2]), "r"(a[3]), "r"(b[0]), "r"(b[1]));
}
__device__ __forceinline__ uint32_t pack_bf(__nv_bfloat16 e0, __nv_bfloat16 e1) {
    return ((uint32_t)__bfloat16_as_ushort(e1) << 16) |
           (uint32_t)__bfloat16_as_ushort(e0);
}
__device__ __forceinline__ void split2(float x0, float x1,
                                       uint32_t& hi, uint32_t& lo) {
    __nv_bfloat16 h0 = __float2bfloat16(x0);
    __nv_bfloat16 h1 = __float2bfloat16(x1);
    __nv_bfloat16 l0 = __float2bfloat16(x0 - __bfloat162float(h0));
    __nv_bfloat16 l1 = __float2bfloat16(x1 - __bfloat162float(h1));
    hi = pack_bf(h0, h1);
    lo = pack_bf(l0, l1);
}

// ---------------------------------------------------------------------------
// Merged fp32 -> bf16 hi/lo converter: all 7 tensors in ONE launch.
// ---------------------------------------------------------------------------
struct ConvPtrs {
    const float* src[7];
    __nv_bfloat16* hi[7];
    __nv_bfloat16* lo[7];
};
__global__ __launch_bounds__(256)
void conv_all(ConvPtrs P)
{
    int b = blockIdx.x, jb, off;
    if (b < 4096)      { jb = 0; off = b; }
    else if (b < 8192) { jb = 1; off = b - 4096; }
    else               { jb = 2 + ((b - 8192) >> 5); off = (b - 8192) & 31; }

    const int i = (off * 256 + threadIdx.x) * 8;
    const float4 a = *(const float4*)(P.src[jb] + i);
    const float4 c = *(const float4*)(P.src[jb] + i + 4);
    uint32_t h0, l0, h1, l1, h2, l2, h3, l3;
    split2(a.x, a.y, h0, l0);
    split2(a.z, a.w, h1, l1);
    split2(c.x, c.y, h2, l2);
    split2(c.z, c.w, h3, l3);
    *(uint4*)(P.hi[jb] + i) = make_uint4(h0, h1, h2, h3);
    *(uint4*)(P.lo[jb] + i) = make_uint4(l0, l1, l2, l3);
}

// ---------------------------------------------------------------------------
// GEMM mainloop: bf16x3 NT-GEMM, CTA 128x128, 8 warps (2m x 4n), warp tile
// 64x32. FOUR-STAGE cp.async pipeline, BK=16 (16 chunks), 3 groups in
// flight -> prefetch distance = 3 MMA blocks (covers L2/DRAM latency).
// Stage = 24KB (4 arrays x 128 rows x 48B; stride-12-word rows are
// ldmatrix-conflict-free: r*12 mod 32 spans 8 distinct banks/phase).
// ---------------------------------------------------------------------------
struct GemmCtx {
    int tid, wid, lane, g, j, wm, wn, m0, n0, rowq, colq, srow, sp;
    uint32_t rowoff, dynb;
};
__device__ __forceinline__ void gemm_main(
    const GemmCtx& C, const __nv_bfloat16* __restrict__ Ah_g,
    const __nv_bfloat16* __restrict__ Al_g,
    const __nv_bfloat16* __restrict__ Bh_g,
    const __nv_bfloat16* __restrict__ Bl_g, float acc[4][4][4])
{
#pragma unroll
    for (int mt = 0; mt < 4; mt++)
#pragma unroll
        for (int nt = 0; nt < 4; nt++)
#pragma unroll
            for (int r = 0; r < 4; r++) acc[mt][nt][r] = 0.f;

    // stage = 24576 B; arrays Ah/Al/Bh/Bl at +0/+6144/+12288/+18432
#define STAGE(c, slot)                                                         \
    do {                                                                       \
        const uint32_t bb = C.dynb + (slot) * 24576;                           \
        const int co = (c) * 16 + C.sp * 8;                                    \
        cp16(bb + C.rowoff,         Ah_g + (C.m0 + C.srow) * 256 + co);        \
        cp16(bb + 6144 + C.rowoff,  Al_g + (C.m0 + C.srow) * 256 + co);        \
        cp16(bb + 12288 + C.rowoff, Bh_g + (C.n0 + C.srow) * 256 + co);        \
        cp16(bb + 18432 + C.rowoff, Bl_g + (C.n0 + C.srow) * 256 + co);        \
        cp_commit();                                                           \
    } while (0)

    STAGE(0, 0);
    STAGE(1, 1);
    STAGE(2, 2);

    for (int c = 0; c < 16; c++) {
        const int slot = c & 3;
        if (c < 14)      cp_wait<2>();   // 3 outstanding -> oldest (c) done
        else if (c == 14) cp_wait<1>();
        else              cp_wait<0>();
        __syncthreads();                 // all warps done with slot (c-1)&3
        if (c + 3 < 16) STAGE(c + 3, (c + 3) & 3);  // overlaps MMAs below

        const uint32_t bufb = C.dynb + slot * 24576;
        const uint32_t cb = (uint32_t)C.colq * 4;
        uint32_t ah[4][4], al[4][4], bhp[2][4], blp[2][4];
#pragma unroll
        for (int mt = 0; mt < 4; mt++) {
            const uint32_t ra =
                (uint32_t)(C.wm * 64 + mt * 16 + C.rowq) * 48 + cb;
            ldsm_x4(ah[mt][0], ah[mt][1], ah[mt][2], ah[mt][3], bufb + ra);
            ldsm_x4(al[mt][0], al[mt][1], al[mt][2], al[mt][3],
                    bufb + 6144 + ra);
        }
#pragma unroll
        for (int np = 0; np < 2; np++) {
            const uint32_t rb =
                (uint32_t)(C.wn * 32 + np * 16 + C.rowq) * 48 + cb;
            ldsm_x4(bhp[np][0], bhp[np][1], bhp[np][2], bhp[np][3],
                    bufb + 12288 + rb);
            ldsm_x4(blp[np][0], blp[np][1], blp[np][2], blp[np][3],
                    bufb + 18432 + rb);
        }
#pragma unroll
        for (int mt = 0; mt < 4; mt++)
#pragma unroll
            for (int nt = 0; nt < 4; nt++) {
                const int np = nt >> 1, sel = nt & 1;
                uint32_t bh2[2] = {bhp[np][sel], bhp[np][sel + 2]};
                uint32_t bl2[2] = {blp[np][sel], blp[np][sel + 2]};
                mma_bf16(acc[mt][nt], ah[mt], bh2);
                mma_bf16(acc[mt][nt], ah[mt], bl2);
                mma_bf16(acc[mt][nt], al[mt], bh2);
            }
    }
#undef STAGE
}

__device__ __forceinline__ GemmCtx make_ctx(uint32_t dynb) {
    GemmCtx C;
    C.tid  = threadIdx.x;
    C.wid  = C.tid >> 5;
    C.lane = C.tid & 31;
    C.g    = C.lane >> 2;
    C.j    = C.lane & 3;
    C.wm   = C.wid & 1;
    C.wn   = C.wid >> 1;
    C.m0   = blockIdx.x * 128;
    C.n0   = blockIdx.y * 128;
    C.rowq = ((C.lane >> 3) & 1) * 8 + (C.lane & 7);
    C.colq = (C.lane >> 4) * 4;
    C.srow = C.tid >> 1;            // 0..127 (row)
    C.sp   = C.tid & 1;             // 16B half of the 32B row
    C.rowoff = (uint32_t)C.srow * 48 + (uint32_t)C.sp * 16;
    C.dynb = dynb;
    return C;
}

// ---------------------------------------------------------------------------
// Merged projection GEMM: grid (256, 2, 4). z: 0=Q, 1=K, 2=V(transposed),
// 3=Gate(sigmoid).
// ---------------------------------------------------------------------------
__global__ __launch_bounds__(256)
void gemm_proj(const __nv_bfloat16* __restrict__ qxh,
               const __nv_bfloat16* __restrict__ qxl,
               const __nv_bfloat16* __restrict__ kvxh,
               const __nv_bfloat16* __restrict__ kvxl,
               const __nv_bfloat16* __restrict__ wqh,
               const __nv_bfloat16* __restrict__ wql,
               const __nv_bfloat16* __restrict__ wkh,
               const __nv_bfloat16* __restrict__ wkl,
               const __nv_bfloat16* __restrict__ wvh,
               const __nv_bfloat16* __restrict__ wvl,
               const __nv_bfloat16* __restrict__ wgh,
               const __nv_bfloat16* __restrict__ wgl,
               const float* __restrict__ bg, float* __restrict__ gbuf,
               __nv_bfloat16* __restrict__ qph, __nv_bfloat16* __restrict__ qpl,
               __nv_bfloat16* __restrict__ kph, __nv_bfloat16* __restrict__ kpl,
               __nv_bfloat16* __restrict__ vph, __nv_bfloat16* __restrict__ vpl)
{
    extern __shared__ uint32_t dyn[];
    const int z = blockIdx.z;

    const __nv_bfloat16* Ah_g = (z == 1 || z == 2) ? kvxh : qxh;
    const __nv_bfloat16* Al_g = (z == 1 || z == 2) ? kvxl : qxl;
    const __nv_bfloat16* Bh_g = (z == 0) ? wqh : (z == 1) ? wkh
                                : (z == 2) ? wvh : wgh;
    const __nv_bfloat16* Bl_g = (z == 0) ? wql : (z == 1) ? wkl
                                : (z == 2) ? wvl : wgl;

    GemmCtx C = make_ctx(smem_u32(dyn));
    float acc[4][4][4];
    gemm_main(C, Ah_g, Al_g, Bh_g, Bl_g, acc);

    __nv_bfloat16* outh = (z == 0) ? qph : (z == 1) ? kph : vph;
    __nv_bfloat16* outl = (z == 0) ? qpl : (z == 1) ? kpl : vpl;

    const int mbase = C.m0 + C.wm * 64;
#pragma unroll
    for (int mt = 0; mt < 4; mt++) {
#pragma unroll
        for (int nt = 0; nt < 4; nt++) {
            const int n = C.n0 + C.wn * 32 + nt * 8 + 2 * C.j;
#pragma unroll
            for (int half = 0; half < 2; half++) {
                const int m = mbase + mt * 16 + C.g + half * 8;
                float2 v = make_float2(acc[mt][nt][half * 2],
                                       acc[mt][nt][half * 2 + 1]);
                const int s = m >> 8, q = m & 255;
                const int h = n >> 5, dh = n & 31;
                if (z < 2) {                 // Q/K: [s][h][q][dh]
                    const int idx = (((s << 3) + h) * 256 + q) * 32 + dh;
                    uint32_t hi, lo;
                    split2(v.x, v.y, hi, lo);
                    *(uint32_t*)(outh + idx) = hi;
                    *(uint32_t*)(outl + idx) = lo;
                } else if (z == 2) {         // V: transposed [s][h][dh][k]
                    const int i0 = (((s << 3) + h) * 32 + dh) * 256 + q;
                    const int i1 = i0 + 256;
                    __nv_bfloat16 h0 = __float2bfloat16(v.x);
                    __nv_bfloat16 h1 = __float2bfloat16(v.y);
                    outh[i0] = h0;
                    outl[i0] = __float2bfloat16(v.x - __bfloat162float(h0));
                    outh[i1] = h1;
                    outl[i1] = __float2bfloat16(v.y - __bfloat162float(h1));
                } else {                     // gate: sigmoid(x+b) fp32
                    const float2 bb = *(const float2*)(bg + n);
                    v.x = 1.f / (1.f + __expf(-(v.x + bb.x)));
                    v.y = 1.f / (1.f + __expf(-(v.y + bb.y)));
                    *(float2*)(gbuf + m * 256 + n) = v;
                }
            }
        }
    }
}

// ---------------------------------------------------------------------------
// Output GEMM: out = O * Wo^T + bo (fp32 to harness buffer)
// ---------------------------------------------------------------------------
__global__ __launch_bounds__(256)
void gemm_out(const __nv_bfloat16* __restrict__ Ah_g,
              const __nv_bfloat16* __restrict__ Al_g,
              const __nv_bfloat16* __restrict__ Bh_g,
              const __nv_bfloat16* __restrict__ Bl_g,
              const float* __restrict__ bias, float* __restrict__ outf)
{
    extern __shared__ uint32_t dyn[];
    GemmCtx C = make_ctx(smem_u32(dyn));
    float acc[4][4][4];
    gemm_main(C, Ah_g, Al_g, Bh_g, Bl_g, acc);

    const int mbase = C.m0 + C.wm * 64;
#pragma unroll
    for (int mt = 0; mt < 4; mt++) {
#pragma unroll
        for (int nt = 0; nt < 4; nt++) {
            const int n = C.n0 + C.wn * 32 + nt * 8 + 2 * C.j;
            const float2 bb = *(const float2*)(bias + n);
#pragma unroll
            for (int half = 0; half < 2; half++) {
                const int m = mbase + mt * 16 + C.g + half * 8;
                float2 v = make_float2(acc[mt][nt][half * 2] + bb.x,
                                       acc[mt][nt][half * 2 + 1] + bb.y);
                *(float2*)(outf + m * 256 + n) = v;
            }
        }
    }
}

// ---------------------------------------------------------------------------
// MMA attention. Grid (s*h, qhalf); 8 warps x 16 q-rows. Chunk = 32 keys.
// bias_pair loads hoisted to chunk top. Fixed-offset softmax (-40).
// ---------------------------------------------------------------------------
__global__ __launch_bounds__(256)
void attn_mma(const __nv_bfloat16* __restrict__ qh_g,
              const __nv_bfloat16* __restrict__ ql_g,
              const __nv_bfloat16* __restrict__ kh_g,
              const __nv_bfloat16* __restrict__ kl_g,
              const __nv_bfloat16* __restrict__ vth_g,
              const __nv_bfloat16* __restrict__ vtl_g,
              const float* __restrict__ gbuf,
              const float* __restrict__ bias_mask,
              const float* __restrict__ bias_pair,
              __nv_bfloat16* __restrict__ obh,
              __nv_bfloat16* __restrict__ obl)
{
    extern __shared__ uint32_t smem[];
    uint32_t* Khi  = smem;
    uint32_t* Klo  = smem + 5120;
    uint32_t* Vthi = smem + 10240;
    uint32_t* Vtlo = smem + 14464;
    float*    bms  = (float*)(smem + 18688);

    const int tid  = threadIdx.x;
    const int wid  = tid >> 5;
    const int lane = tid & 31;
    const int g    = lane >> 2;
    const int j    = lane & 3;
    const int sh   = blockIdx.x;
    const int s    = sh >> 3;
    const int h    = sh & 7;
    const int q0w  = blockIdx.y * 128 + wid * 16;

    {
        const __nv_bfloat16* ksh = kh_g + sh * 256 * 32;
        const __nv_bfloat16* ksl = kl_g + sh * 256 * 32;
        const __nv_bfloat16* vsh = vth_g + sh * 32 * 256;
        const __nv_bfloat16* vsl = vtl_g + sh * 32 * 256;
        const uint32_t khb = smem_u32(Khi), klb = smem_u32(Klo);
        const uint32_t vhb = smem_u32(Vthi), vlb = smem_u32(Vtlo);
#pragma unroll
        for (int it = 0; it < 4; it++) {
            const int ic  = it * 256 + tid;
            const int key = ic >> 2, part = ic & 3;
            cp16(khb + key * 80 + part * 16, ksh + key * 32 + part * 8);
            cp16(klb + key * 80 + part * 16, ksl + key * 32 + part * 8);
            const int d = ic >> 5, p5 = ic & 31;
            cp16(vhb + d * 528 + p5 * 16, vsh + d * 256 + p5 * 8);
            cp16(vlb + d * 528 + p5 * 16, vsl + d * 256 + p5 * 8);
        }
        cp_commit();
        bms[tid] = bias_mask[s * 256 + tid] - 40.f;
        cp_wait<0>();
    }
    __syncthreads();

    const __nv_bfloat16* qh = qh_g + (sh * 256 + q0w) * 32;
    const __nv_bfloat16* ql = ql_g + (sh * 256 + q0w) * 32;
    uint32_t aQh[2][4], aQl[2][4];
#pragma unroll
    for (int u = 0; u < 2; u++) {
        aQh[u][0] = *(const uint32_t*)(qh + g * 32 + u * 16 + 2 * j);
        aQh[u][1] = *(const uint32_t*)(qh + (g + 8) * 32 + u * 16 + 2 * j);
        aQh[u][2] = *(const uint32_t*)(qh + g * 32 + u * 16 + 8 + 2 * j);
        aQh[u][3] = *(const uint32_t*)(qh + (g + 8) * 32 + u * 16 + 8 + 2 * j);
        aQl[u][0] = *(const uint32_t*)(ql + g * 32 + u * 16 + 2 * j);
        aQl[u][1] = *(const uint32_t*)(ql + (g + 8) * 32 + u * 16 + 2 * j);
        aQl[u][2] = *(const uint32_t*)(ql + g * 32 + u * 16 + 8 + 2 * j);
        aQl[u][3] = *(const uint32_t*)(ql + (g + 8) * 32 + u * 16 + 8 + 2 * j);
    }

    float oacc[4][4];
#pragma unroll
    for (int nt = 0; nt < 4; nt++)
#pragma unroll
        for (int r = 0; r < 4; r++) oacc[nt][r] = 0.f;
    float lg = 0.f, lg8 = 0.f;

    const float* bp = bias_pair + h * 65536;

    for (int c = 0; c < 8; c++) {
        const int kc = c * 32;

        float2 bpf0[4], bpf1[4];
#pragma unroll
        for (int t = 0; t < 4; t++) {
            const int col = kc + 8 * t + 2 * j;
            bpf0[t] = *(const float2*)(bp + (q0w + g) * 256 + col);
            bpf1[t] = *(const float2*)(bp + (q0w + g + 8) * 256 + col);
        }

        float d[4][4];
#pragma unroll
        for (int t = 0; t < 4; t++)
#pragma unroll
            for (int r = 0; r < 4; r++) d[t][r] = 0.f;
#pragma unroll
        for (int u = 0; u < 2; u++) {
#pragma unroll
            for (int t = 0; t < 4; t++) {
                const int kr = (kc + 8 * t + g) * 20;
                uint32_t bh[2] = {Khi[kr + 8 * u + j], Khi[kr + 8 * u + j + 4]};
                uint32_t bl[2] = {Klo[kr + 8 * u + j], Klo[kr + 8 * u + j + 4]};
                mma_bf16(d[t], aQh[u], bh);
                mma_bf16(d[t], aQh[u], bl);
                mma_bf16(d[t], aQl[u], bh);
            }
        }

        float p[4][4];
#pragma unroll
        for (int t = 0; t < 4; t++) {
            const int col = kc + 8 * t + 2 * j;
            const float bm0 = bms[col], bm1 = bms[col + 1];
            p[t][0] = __expf(d[t][0] + bm0 + bpf0[t].x);
            p[t][1] = __expf(d[t][1] + bm1 + bpf0[t].y);
            p[t][2] = __expf(d[t][2] + bm0 + bpf1[t].x);
            p[t][3] = __expf(d[t][3] + bm1 + bpf1[t].y);
            lg  += p[t][0] + p[t][1];
            lg8 += p[t][2] + p[t][3];
        }

        uint32_t ah[2][4], al[2][4];
#pragma unroll
        for (int u2 = 0; u2 < 2; u2++) {
            split2(p[2 * u2][0],     p[2 * u2][1],     ah[u2][0], al[u2][0]);
            split2(p[2 * u2][2],     p[2 * u2][3],     ah[u2][1], al[u2][1]);
            split2(p[2 * u2 + 1][0], p[2 * u2 + 1][1], ah[u2][2], al[u2][2]);
            split2(p[2 * u2 + 1][2], p[2 * u2 + 1][3], ah[u2][3], al[u2][3]);
        }

#pragma unroll
        for (int u2 = 0; u2 < 2; u2++) {
            const int kw = c * 16 + u2 * 8;
#pragma unroll
            for (int nt = 0; nt < 4; nt++) {
                const int vr = (nt * 8 + g) * 132;
                uint32_t bvh[2] = {Vthi[vr + kw + j], Vthi[vr + kw + j + 4]};
                uint32_t bvl[2] = {Vtlo[vr + kw + j], Vtlo[vr + kw + j + 4]};
                mma_bf16(oacc[nt], ah[u2], bvh);
                mma_bf16(oacc[nt], ah[u2], bvl);
                mma_bf16(oacc[nt], al[u2], bvh);
            }
        }
    }

    lg  += __shfl_xor_sync(0xffffffff, lg, 1);
    lg  += __shfl_xor_sync(0xffffffff, lg, 2);
    lg8 += __shfl_xor_sync(0xffffffff, lg8, 1);
    lg8 += __shfl_xor_sync(0xffffffff, lg8, 2);
    const float il  = 1.f / lg;
    const float il8 = 1.f / lg8;

    const int r0 = s * 256 + q0w + g;
    const int r1 = r0 + 8;
#pragma unroll
    for (int nt = 0; nt < 4; nt++) {
        const int colb = h * 32 + nt * 8 + 2 * j;
        const float2 g0 = *(const float2*)(gbuf + r0 * 256 + colb);
        const float2 g1 = *(const float2*)(gbuf + r1 * 256 + colb);
        uint32_t hi, lo;
        split2(oacc[nt][0] * il * g0.x, oacc[nt][1] * il * g0.y, hi, lo);
        *(uint32_t*)(obh + r0 * 256 + colb) = hi;
        *(uint32_t*)(obl + r0 * 256 + colb) = lo;
        split2(oacc[nt][2] * il8 * g1.x, oacc[nt][3] * il8 * g1.y, hi, lo);
        *(uint32_t*)(obh + r1 * 256 + colb) = hi;
        *(uint32_t*)(obl + r1 * 256 + colb) = lo;
    }
}

// ---------------------------------------------------------------------------
// Launch: 4 kernels (conv, merged proj, attention, out-GEMM)
// ---------------------------------------------------------------------------
extern "C" void kernel_launch(void* const* d_in, const int* in_sizes, int n_in,
                              void* d_out, int out_size)
{
    const float* q_x   = (const float*)d_in[0];
    const float* kv_x  = (const float*)d_in[1];
    const float* bmask = (const float*)d_in[2];
    const float* bpair = (const float*)d_in[3];
    const float* Wq    = (const float*)d_in[4];
    const float* Wk    = (const float*)d_in[5];
    const float* Wv    = (const float*)d_in[6];
    const float* Wg    = (const float*)d_in[7];
    const float* bg    = (const float*)d_in[8];
    const float* Wo    = (const float*)d_in[9];
    const float* bo    = (const float*)d_in[10];
    float* out = (float*)d_out;

    auto get = [](const void* sym) {
        void* p;
        cudaGetSymbolAddress(&p, sym);
        return (__nv_bfloat16*)p;
    };
    __nv_bfloat16 *qxh = get(g_qxh4),  *qxl = get(g_qxl4);
    __nv_bfloat16 *kvxh = get(g_kvxh4), *kvxl = get(g_kvxl4);
    __nv_bfloat16 *wqh = get(g_wqh4), *wql = get(g_wql4);
    __nv_bfloat16 *wkh = get(g_wkh4), *wkl = get(g_wkl4);
    __nv_bfloat16 *wvh = get(g_wvh4), *wvl = get(g_wvl4);
    __nv_bfloat16 *wgh = get(g_wgh4), *wgl = get(g_wgl4);
    __nv_bfloat16 *woh = get(g_woh4), *wol = get(g_wol4);
    __nv_bfloat16 *qph = get(g_qhi4), *qpl = get(g_qlo4);
    __nv_bfloat16 *kph = get(g_khi4), *kpl = get(g_klo4);
    __nv_bfloat16 *vph = get(g_vthi4), *vpl = get(g_vtlo4);
    __nv_bfloat16 *obh = get(g_obh4), *obl = get(g_obl4);
    float* gbp;
    cudaGetSymbolAddress((void**)&gbp, g_gbuf);

    const int gsm = 98304;   // 4 stages x 24KB
    cudaFuncSetAttribute(gemm_proj, cudaFuncAttributeMaxDynamicSharedMemorySize, gsm);
    cudaFuncSetAttribute(gemm_out,  cudaFuncAttributeMaxDynamicSharedMemorySize, gsm);
    cudaFuncSetAttribute(attn_mma,  cudaFuncAttributeMaxDynamicSharedMemorySize, 75776);

    ConvPtrs P;
    P.src[0] = q_x;  P.hi[0] = qxh;  P.lo[0] = qxl;
    P.src[1] = kv_x; P.hi[1] = kvxh; P.lo[1] = kvxl;
    P.src[2] = Wq;   P.hi[2] = wqh;  P.lo[2] = wql;
    P.src[3] = Wk;   P.hi[3] = wkh;  P.lo[3] = wkl;
    P.src[4] = Wv;   P.hi[4] = wvh;  P.lo[4] = wvl;
    P.src[5] = Wg;   P.hi[5] = wgh;  P.lo[5] = wgl;
    P.src[6] = Wo;   P.hi[6] = woh;  P.lo[6] = wol;
    conv_all<<<8352, 256>>>(P);

    gemm_proj<<<dim3(M_ROWS / 128, 2, 4), 256, gsm>>>(
        qxh, qxl, kvxh, kvxl, wqh, wql, wkh, wkl, wvh, wvl, wgh, wgl,
        bg, gbp, qph, qpl, kph, kpl, vph, vpl);

    attn_mma<<<dim3(S_DIM * H_DIM, 2), 256, 75776>>>(
        qph, qpl, kph, kpl, vph, vpl, gbp, bmask, bpair, obh, obl);

    gemm_out<<<dim3(M_ROWS / 128, 2), 256, gsm>>>(obh, obl, woh, wol, bo, out);
}

// round 16
// speedup vs baseline: 1.1243x; 1.1243x over previous
#include <cuda_runtime.h>
#include <cuda_bf16.h>
#include <cuda_fp16.h>
#include <cstdint>

// ---------------------------------------------------------------------------
// Problem constants
// ---------------------------------------------------------------------------
#define S_DIM 128
#define Q_DIM 256
#define C_DIM 256
#define H_DIM 8
#define DH_DIM 32
#define M_ROWS (S_DIM * Q_DIM)        // 32768

// ---------------------------------------------------------------------------
// Scratch (static device globals). uint4 => 16B align.
// bf16 split (x3 path): q_x, kv_x, Wq, Wk; proj outs Q/K/V.
// fp16 split/single (x2 path): q_x, kv_x, Wv, Wg, Wo, attn out O.
// ---------------------------------------------------------------------------
#define XU4 (M_ROWS * 256 / 8)
#define WU4 (256 * 256 / 8)
__device__ uint4 g_qxh4[XU4],  g_qxl4[XU4];    // bf16 h/l q_x
__device__ uint4 g_kvxh4[XU4], g_kvxl4[XU4];   // bf16 h/l kv_x
__device__ uint4 g_qxfh4[XU4],  g_qxfl4[XU4];  // fp16 h/l q_x
__device__ uint4 g_kvxfh4[XU4], g_kvxfl4[XU4]; // fp16 h/l kv_x
__device__ uint4 g_wqh4[WU4], g_wql4[WU4];     // bf16 h/l Wq
__device__ uint4 g_wkh4[WU4], g_wkl4[WU4];     // bf16 h/l Wk
__device__ uint4 g_wvf4[WU4];                  // fp16 single Wv
__device__ uint4 g_wgf4[WU4];                  // fp16 single Wg
__device__ uint4 g_wof4[WU4];                  // fp16 single Wo
__device__ uint4 g_qhi4[XU4], g_qlo4[XU4];     // Q proj bf16 [s][h][q][dh]
__device__ uint4 g_khi4[XU4], g_klo4[XU4];     // K proj bf16 [s][h][q][dh]
__device__ uint4 g_vthi4[XU4], g_vtlo4[XU4];   // V proj bf16 [s][h][dh][k]
__device__ uint4 g_obh4[XU4], g_obl4[XU4];     // attn out fp16 h/l [m][tot]
__device__ float g_gbuf[M_ROWS * C_DIM];

// ---------------------------------------------------------------------------
// Helpers
// ---------------------------------------------------------------------------
__device__ __forceinline__ uint32_t smem_u32(const void* p) {
    uint32_t a;
    asm("{ .reg .u64 t; cvta.to.shared.u64 t, %1; cvt.u32.u64 %0, t; }"
        : "=r"(a) : "l"(p));
    return a;
}
__device__ __forceinline__ void cp16(uint32_t dst, const void* src) {
    asm volatile("cp.async.cg.shared.global [%0], [%1], 16;"
                 :: "r"(dst), "l"(src) : "memory");
}
__device__ __forceinline__ void cp_commit() {
    asm volatile("cp.async.commit_group;" ::: "memory");
}
template <int N>
__device__ __forceinline__ void cp_wait() {
    asm volatile("cp.async.wait_group %0;" :: "n"(N) : "memory");
}
__device__ __forceinline__ void ldsm_x4(uint32_t& r0, uint32_t& r1,
                                        uint32_t& r2, uint32_t& r3,
                                        uint32_t addr) {
    asm volatile("ldmatrix.sync.aligned.m8n8.x4.shared.b16 {%0,%1,%2,%3}, [%4];"
                 : "=r"(r0), "=r"(r1), "=r"(r2), "=r"(r3) : "r"(addr));
}
__device__ __forceinline__ void mma_bf16(float* d, const uint32_t* a,
                                         const uint32_t* b) {
    asm volatile(
        "mma.sync.aligned.m16n8k16.row.col.f32.bf16.bf16.f32 "
        "{%0,%1,%2,%3}, {%4,%5,%6,%7}, {%8,%9}, {%0,%1,%2,%3};"
        : "+f"(d[0]), "+f"(d[1]), "+f"(d[2]), "+f"(d[3])
        : "r"(a[0]), "r"(a[1]), "r"(a[2]), "r"(a[3]), "r"(b[0]), "r"(b[1]));
}
__device__ __forceinline__ void mma_f16(float* d, const uint32_t* a,
                                        const uint32_t* b) {
    asm volatile(
        "mma.sync.aligned.m16n8k16.row.col.f32.f16.f16.f32 "
        "{%0,%1,%2,%3}, {%4,%5,%6,%7}, {%8,%9}, {%0,%1,%2,%3};"
        : "+f"(d[0]), "+f"(d[1]), "+f"(d[2]), "+f"(d[3])
        : "r"(a[0]), "r"(a[1]), "r"(a[2]), "r"(a[3]), "r"(b[0]), "r"(b[1]));
}
__device__ __forceinline__ uint32_t pack_bf(__nv_bfloat16 e0, __nv_bfloat16 e1) {
    return ((uint32_t)__bfloat16_as_ushort(e1) << 16) |
           (uint32_t)__bfloat16_as_ushort(e0);
}
__device__ __forceinline__ void split2(float x0, float x1,
                                       uint32_t& hi, uint32_t& lo) {
    __nv_bfloat16 h0 = __float2bfloat16(x0);
    __nv_bfloat16 h1 = __float2bfloat16(x1);
    __nv_bfloat16 l0 = __float2bfloat16(x0 - __bfloat162float(h0));
    __nv_bfloat16 l1 = __float2bfloat16(x1 - __bfloat162float(h1));
    hi = pack_bf(h0, h1);
    lo = pack_bf(l0, l1);
}
__device__ __forceinline__ uint32_t pack_h(__half e0, __half e1) {
    return ((uint32_t)__half_as_ushort(e1) << 16) |
           (uint32_t)__half_as_ushort(e0);
}
__device__ __forceinline__ void split2h(float x0, float x1,
                                        uint32_t& hi, uint32_t& lo) {
    __half h0 = __float2half(x0);
    __half h1 = __float2half(x1);
    __half l0 = __float2half(x0 - __half2float(h0));
    __half l1 = __float2half(x1 - __half2float(h1));
    hi = pack_h(h0, h1);
    lo = pack_h(l0, l1);
}

// ---------------------------------------------------------------------------
// Merged converter. jb 0,1 (q_x,kv_x): bf16 h/l + fp16 h/l.
// jb 2,3 (Wq,Wk): bf16 h/l. jb 4,5,6 (Wv,Wg,Wo): fp16 single.
// ---------------------------------------------------------------------------
struct ConvPtrs {
    const float* src[7];
    __nv_bfloat16* bh[7];
    __nv_bfloat16* bl[7];
    __half* fh[7];
    __half* fl[7];
    __half* fs[7];
};
__global__ __launch_bounds__(256)
void conv_all(ConvPtrs P)
{
    int b = blockIdx.x, jb, off;
    if (b < 4096)      { jb = 0; off = b; }
    else if (b < 8192) { jb = 1; off = b - 4096; }
    else               { jb = 2 + ((b - 8192) >> 5); off = (b - 8192) & 31; }

    const int i = (off * 256 + threadIdx.x) * 8;
    float v[8];
    *(float4*)(v)     = *(const float4*)(P.src[jb] + i);
    *(float4*)(v + 4) = *(const float4*)(P.src[jb] + i + 4);

    if (jb < 4) {
        uint32_t h[4], l[4];
#pragma unroll
        for (int k = 0; k < 4; k++) split2(v[2*k], v[2*k+1], h[k], l[k]);
        *(uint4*)(P.bh[jb] + i) = make_uint4(h[0], h[1], h[2], h[3]);
        *(uint4*)(P.bl[jb] + i) = make_uint4(l[0], l[1], l[2], l[3]);
        if (jb < 2) {
#pragma unroll
            for (int k = 0; k < 4; k++) split2h(v[2*k], v[2*k+1], h[k], l[k]);
            *(uint4*)(P.fh[jb] + i) = make_uint4(h[0], h[1], h[2], h[3]);
            *(uint4*)(P.fl[jb] + i) = make_uint4(l[0], l[1], l[2], l[3]);
        }
    } else {
        uint32_t s[4];
#pragma unroll
        for (int k = 0; k < 4; k++)
            s[k] = pack_h(__float2half(v[2*k]), __float2half(v[2*k+1]));
        *(uint4*)(P.fs[jb] + i) = make_uint4(s[0], s[1], s[2], s[3]);
    }
}

// ---------------------------------------------------------------------------
// Shared GEMM context
// ---------------------------------------------------------------------------
struct GemmCtx {
    int tid, wid, lane, g, j, wm, wn, m0, n0, rowq, colq, srow, sp;
    uint32_t rowoff, dynb;
};
__device__ __forceinline__ GemmCtx make_ctx(uint32_t dynb) {
    GemmCtx C;
    C.tid  = threadIdx.x;
    C.wid  = C.tid >> 5;
    C.lane = C.tid & 31;
    C.g    = C.lane >> 2;
    C.j    = C.lane & 3;
    C.wm   = C.wid & 1;
    C.wn   = C.wid >> 1;
    C.m0   = blockIdx.x * 128;
    C.n0   = blockIdx.y * 128;
    C.rowq = ((C.lane >> 3) & 1) * 8 + (C.lane & 7);
    C.colq = (C.lane >> 4) * 4;
    C.srow = C.tid >> 1;
    C.sp   = (C.tid & 1) * 2;
    C.rowoff = (uint32_t)C.srow * 80 + (uint32_t)C.sp * 16;
    C.dynb = dynb;
    return C;
}

// ---------------------------------------------------------------------------
// bf16x3 mainloop (R12-exact, 400.3us config): BK=32, 2-stage, single sync.
// Stage 40960B: Ah/Al/Bh/Bl at +0/+10240/+20480/+30720, 80B row stride.
// ---------------------------------------------------------------------------
__device__ __forceinline__ void gemm_main(
    const GemmCtx& C, const __nv_bfloat16* __restrict__ Ah_g,
    const __nv_bfloat16* __restrict__ Al_g,
    const __nv_bfloat16* __restrict__ Bh_g,
    const __nv_bfloat16* __restrict__ Bl_g, float acc[4][4][4])
{
#pragma unroll
    for (int mt = 0; mt < 4; mt++)
#pragma unroll
        for (int nt = 0; nt < 4; nt++)
#pragma unroll
            for (int r = 0; r < 4; r++) acc[mt][nt][r] = 0.f;

#define STAGE(c, b)                                                            \
    do {                                                                       \
        const uint32_t bb = C.dynb + (b) * 40960;                              \
        const int co = (c) * 32 + C.sp * 8;                                    \
        cp16(bb + C.rowoff,              Ah_g + (C.m0 + C.srow) * 256 + co);   \
        cp16(bb + C.rowoff + 16,         Ah_g + (C.m0 + C.srow) * 256 + co + 8);\
        cp16(bb + 10240 + C.rowoff,      Al_g + (C.m0 + C.srow) * 256 + co);   \
        cp16(bb + 10240 + C.rowoff + 16, Al_g + (C.m0 + C.srow) * 256 + co + 8);\
        cp16(bb + 20480 + C.rowoff,      Bh_g + (C.n0 + C.srow) * 256 + co);   \
        cp16(bb + 20480 + C.rowoff + 16, Bh_g + (C.n0 + C.srow) * 256 + co + 8);\
        cp16(bb + 30720 + C.rowoff,      Bl_g + (C.n0 + C.srow) * 256 + co);   \
        cp16(bb + 30720 + C.rowoff + 16, Bl_g + (C.n0 + C.srow) * 256 + co + 8);\
        cp_commit();                                                           \
    } while (0)

    STAGE(0, 0);
    for (int c = 0; c < 8; c++) {
        const int b = c & 1;
        cp_wait<0>();
        __syncthreads();
        if (c < 7) STAGE(c + 1, b ^ 1);

        const uint32_t bufb = C.dynb + b * 40960;
#pragma unroll
        for (int kt = 0; kt < 2; kt++) {
            const uint32_t cb = (uint32_t)(kt * 8 + C.colq) * 4;
            uint32_t ah[4][4], al[4][4], bhp[2][4], blp[2][4];
#pragma unroll
            for (int mt = 0; mt < 4; mt++) {
                const uint32_t ra =
                    (uint32_t)(C.wm * 64 + mt * 16 + C.rowq) * 80 + cb;
                ldsm_x4(ah[mt][0], ah[mt][1], ah[mt][2], ah[mt][3], bufb + ra);
                ldsm_x4(al[mt][0], al[mt][1], al[mt][2], al[mt][3],
                        bufb + 10240 + ra);
            }
#pragma unroll
            for (int np = 0; np < 2; np++) {
                const uint32_t rb =
                    (uint32_t)(C.wn * 32 + np * 16 + C.rowq) * 80 + cb;
                ldsm_x4(bhp[np][0], bhp[np][1], bhp[np][2], bhp[np][3],
                        bufb + 20480 + rb);
                ldsm_x4(blp[np][0], blp[np][1], blp[np][2], blp[np][3],
                        bufb + 30720 + rb);
            }
#pragma unroll
            for (int mt = 0; mt < 4; mt++)
#pragma unroll
                for (int nt = 0; nt < 4; nt++) {
                    const int np = nt >> 1, sel = nt & 1;
                    uint32_t bh2[2] = {bhp[np][sel], bhp[np][sel + 2]};
                    uint32_t bl2[2] = {blp[np][sel], blp[np][sel + 2]};
                    mma_bf16(acc[mt][nt], ah[mt], bh2);
                    mma_bf16(acc[mt][nt], ah[mt], bl2);
                    mma_bf16(acc[mt][nt], al[mt], bh2);
                }
        }
    }
#undef STAGE
}

// ---------------------------------------------------------------------------
// fp16x2 mainloop: A split fp16 hi/lo (exact to 2^-21), B single fp16.
// 2 MMAs/tile, 3 smem arrays. Stage 30720B: Ah/Al/Bs at +0/+10240/+20480.
// ---------------------------------------------------------------------------
__device__ __forceinline__ void gemm_main_f16(
    const GemmCtx& C, const __half* __restrict__ Ah_g,
    const __half* __restrict__ Al_g,
    const __half* __restrict__ Bs_g, float acc[4][4][4])
{
#pragma unroll
    for (int mt = 0; mt < 4; mt++)
#pragma unroll
        for (int nt = 0; nt < 4; nt++)
#pragma unroll
            for (int r = 0; r < 4; r++) acc[mt][nt][r] = 0.f;

#define STAGEH(c, b)                                                           \
    do {                                                                       \
        const uint32_t bb = C.dynb + (b) * 30720;                              \
        const int co = (c) * 32 + C.sp * 8;                                    \
        cp16(bb + C.rowoff,              Ah_g + (C.m0 + C.srow) * 256 + co);   \
        cp16(bb + C.rowoff + 16,         Ah_g + (C.m0 + C.srow) * 256 + co + 8);\
        cp16(bb + 10240 + C.rowoff,      Al_g + (C.m0 + C.srow) * 256 + co);   \
        cp16(bb + 10240 + C.rowoff + 16, Al_g + (C.m0 + C.srow) * 256 + co + 8);\
        cp16(bb + 20480 + C.rowoff,      Bs_g + (C.n0 + C.srow) * 256 + co);   \
        cp16(bb + 20480 + C.rowoff + 16, Bs_g + (C.n0 + C.srow) * 256 + co + 8);\
        cp_commit();                                                           \
    } while (0)

    STAGEH(0, 0);
    for (int c = 0; c < 8; c++) {
        const int b = c & 1;
        cp_wait<0>();
        __syncthreads();
        if (c < 7) STAGEH(c + 1, b ^ 1);

        const uint32_t bufb = C.dynb + b * 30720;
#pragma unroll
        for (int kt = 0; kt < 2; kt++) {
            const uint32_t cb = (uint32_t)(kt * 8 + C.colq) * 4;
            uint32_t ah[4][4], al[4][4], bp[2][4];
#pragma unroll
            for (int mt = 0; mt < 4; mt++) {
                const uint32_t ra =
                    (uint32_t)(C.wm * 64 + mt * 16 + C.rowq) * 80 + cb;
                ldsm_x4(ah[mt][0], ah[mt][1], ah[mt][2], ah[mt][3], bufb + ra);
                ldsm_x4(al[mt][0], al[mt][1], al[mt][2], al[mt][3],
                        bufb + 10240 + ra);
            }
#pragma unroll
            for (int np = 0; np < 2; np++) {
                const uint32_t rb =
                    (uint32_t)(C.wn * 32 + np * 16 + C.rowq) * 80 + cb;
                ldsm_x4(bp[np][0], bp[np][1], bp[np][2], bp[np][3],
                        bufb + 20480 + rb);
            }
#pragma unroll
            for (int mt = 0; mt < 4; mt++)
#pragma unroll
                for (int nt = 0; nt < 4; nt++) {
                    const int np = nt >> 1, sel = nt & 1;
                    uint32_t b2[2] = {bp[np][sel], bp[np][sel + 2]};
                    mma_f16(acc[mt][nt], ah[mt], b2);
                    mma_f16(acc[mt][nt], al[mt], b2);
                }
        }
    }
#undef STAGEH
}

// ---------------------------------------------------------------------------
// Merged projection GEMM: grid (256, 2, 4).
// z=0 Q (bf16x3), z=1 K (bf16x3), z=2 V (fp16x2, transposed bf16-split out),
// z=3 gate (fp16x2, sigmoid fp32 out).
// ---------------------------------------------------------------------------
__global__ __launch_bounds__(256)
void gemm_proj(const __nv_bfloat16* __restrict__ qxh,
               const __nv_bfloat16* __restrict__ qxl,
               const __nv_bfloat16* __restrict__ kvxh,
               const __nv_bfloat16* __restrict__ kvxl,
               const __half* __restrict__ qxfh, const __half* __restrict__ qxfl,
               const __half* __restrict__ kvxfh, const __half* __restrict__ kvxfl,
               const __nv_bfloat16* __restrict__ wqh,
               const __nv_bfloat16* __restrict__ wql,
               const __nv_bfloat16* __restrict__ wkh,
               const __nv_bfloat16* __restrict__ wkl,
               const __half* __restrict__ wvf, const __half* __restrict__ wgf,
               const float* __restrict__ bg, float* __restrict__ gbuf,
               __nv_bfloat16* __restrict__ qph, __nv_bfloat16* __restrict__ qpl,
               __nv_bfloat16* __restrict__ kph, __nv_bfloat16* __restrict__ kpl,
               __nv_bfloat16* __restrict__ vph, __nv_bfloat16* __restrict__ vpl)
{
    extern __shared__ uint32_t dyn[];
    const int z = blockIdx.z;
    GemmCtx C = make_ctx(smem_u32(dyn));
    float acc[4][4][4];

    if (z == 0)      gemm_main(C, qxh, qxl, wqh, wql, acc);
    else if (z == 1) gemm_main(C, kvxh, kvxl, wkh, wkl, acc);
    else if (z == 2) gemm_main_f16(C, kvxfh, kvxfl, wvf, acc);
    else             gemm_main_f16(C, qxfh, qxfl, wgf, acc);

    __nv_bfloat16* outh = (z == 0) ? qph : (z == 1) ? kph : vph;
    __nv_bfloat16* outl = (z == 0) ? qpl : (z == 1) ? kpl : vpl;

    const int mbase = C.m0 + C.wm * 64;
#pragma unroll
    for (int mt = 0; mt < 4; mt++) {
#pragma unroll
        for (int nt = 0; nt < 4; nt++) {
            const int n = C.n0 + C.wn * 32 + nt * 8 + 2 * C.j;
#pragma unroll
            for (int half = 0; half < 2; half++) {
                const int m = mbase + mt * 16 + C.g + half * 8;
                float2 v = make_float2(acc[mt][nt][half * 2],
                                       acc[mt][nt][half * 2 + 1]);
                const int s = m >> 8, q = m & 255;
                const int h = n >> 5, dh = n & 31;
                if (z < 2) {                 // Q/K: bf16 split [s][h][q][dh]
                    const int idx = (((s << 3) + h) * 256 + q) * 32 + dh;
                    uint32_t hi, lo;
                    split2(v.x, v.y, hi, lo);
                    *(uint32_t*)(outh + idx) = hi;
                    *(uint32_t*)(outl + idx) = lo;
                } else if (z == 2) {         // V: transposed bf16 split
                    const int i0 = (((s << 3) + h) * 32 + dh) * 256 + q;
                    const int i1 = i0 + 256;
                    __nv_bfloat16 h0 = __float2bfloat16(v.x);
                    __nv_bfloat16 h1 = __float2bfloat16(v.y);
                    outh[i0] = h0;
                    outl[i0] = __float2bfloat16(v.x - __bfloat162float(h0));
                    outh[i1] = h1;
                    outl[i1] = __float2bfloat16(v.y - __bfloat162float(h1));
                } else {                     // gate: sigmoid fp32
                    const float2 bb = *(const float2*)(bg + n);
                    v.x = 1.f / (1.f + __expf(-(v.x + bb.x)));
                    v.y = 1.f / (1.f + __expf(-(v.y + bb.y)));
                    *(float2*)(gbuf + m * 256 + n) = v;
                }
            }
        }
    }
}

// ---------------------------------------------------------------------------
// Output GEMM (fp16x2): out = O * Wo^T + bo
// ---------------------------------------------------------------------------
__global__ __launch_bounds__(256)
void gemm_out(const __half* __restrict__ Ah_g, const __half* __restrict__ Al_g,
              const __half* __restrict__ Bs_g,
              const float* __restrict__ bias, float* __restrict__ outf)
{
    extern __shared__ uint32_t dyn[];
    GemmCtx C = make_ctx(smem_u32(dyn));
    float acc[4][4][4];
    gemm_main_f16(C, Ah_g, Al_g, Bs_g, acc);

    const int mbase = C.m0 + C.wm * 64;
#pragma unroll
    for (int mt = 0; mt < 4; mt++) {
#pragma unroll
        for (int nt = 0; nt < 4; nt++) {
            const int n = C.n0 + C.wn * 32 + nt * 8 + 2 * C.j;
            const float2 bb = *(const float2*)(bias + n);
#pragma unroll
            for (int half = 0; half < 2; half++) {
                const int m = mbase + mt * 16 + C.g + half * 8;
                float2 v = make_float2(acc[mt][nt][half * 2] + bb.x,
                                       acc[mt][nt][half * 2 + 1] + bb.y);
                *(float2*)(outf + m * 256 + n) = v;
            }
        }
    }
}

// ---------------------------------------------------------------------------
// MMA attention (R12-validated). Output now split to fp16 hi/lo.
// ---------------------------------------------------------------------------
__global__ __launch_bounds__(256)
void attn_mma(const __nv_bfloat16* __restrict__ qh_g,
              const __nv_bfloat16* __restrict__ ql_g,
              const __nv_bfloat16* __restrict__ kh_g,
              const __nv_bfloat16* __restrict__ kl_g,
              const __nv_bfloat16* __restrict__ vth_g,
              const __nv_bfloat16* __restrict__ vtl_g,
              const float* __restrict__ gbuf,
              const float* __restrict__ bias_mask,
              const float* __restrict__ bias_pair,
              __half* __restrict__ obh, __half* __restrict__ obl)
{
    extern __shared__ uint32_t smem[];
    uint32_t* Khi  = smem;
    uint32_t* Klo  = smem + 5120;
    uint32_t* Vthi = smem + 10240;
    uint32_t* Vtlo = smem + 14464;
    float*    bms  = (float*)(smem + 18688);

    const int tid  = threadIdx.x;
    const int wid  = tid >> 5;
    const int lane = tid & 31;
    const int g    = lane >> 2;
    const int j    = lane & 3;
    const int sh   = blockIdx.x;
    const int s    = sh >> 3;
    const int h    = sh & 7;
    const int q0w  = blockIdx.y * 128 + wid * 16;

    {
        const __nv_bfloat16* ksh = kh_g + sh * 256 * 32;
        const __nv_bfloat16* ksl = kl_g + sh * 256 * 32;
        const __nv_bfloat16* vsh = vth_g + sh * 32 * 256;
        const __nv_bfloat16* vsl = vtl_g + sh * 32 * 256;
        const uint32_t khb = smem_u32(Khi), klb = smem_u32(Klo);
        const uint32_t vhb = smem_u32(Vthi), vlb = smem_u32(Vtlo);
#pragma unroll
        for (int it = 0; it < 4; it++) {
            const int ic  = it * 256 + tid;
            const int key = ic >> 2, part = ic & 3;
            cp16(khb + key * 80 + part * 16, ksh + key * 32 + part * 8);
            cp16(klb + key * 80 + part * 16, ksl + key * 32 + part * 8);
            const int d = ic >> 5, p5 = ic & 31;
            cp16(vhb + d * 528 + p5 * 16, vsh + d * 256 + p5 * 8);
            cp16(vlb + d * 528 + p5 * 16, vsl + d * 256 + p5 * 8);
        }
        cp_commit();
        bms[tid] = bias_mask[s * 256 + tid] - 40.f;
        cp_wait<0>();
    }
    __syncthreads();

    const __nv_bfloat16* qh = qh_g + (sh * 256 + q0w) * 32;
    const __nv_bfloat16* ql = ql_g + (sh * 256 + q0w) * 32;
    uint32_t aQh[2][4], aQl[2][4];
#pragma unroll
    for (int u = 0; u < 2; u++) {
        aQh[u][0] = *(const uint32_t*)(qh + g * 32 + u * 16 + 2 * j);
        aQh[u][1] = *(const uint32_t*)(qh + (g + 8) * 32 + u * 16 + 2 * j);
        aQh[u][2] = *(const uint32_t*)(qh + g * 32 + u * 16 + 8 + 2 * j);
        aQh[u][3] = *(const uint32_t*)(qh + (g + 8) * 32 + u * 16 + 8 + 2 * j);
        aQl[u][0] = *(const uint32_t*)(ql + g * 32 + u * 16 + 2 * j);
        aQl[u][1] = *(const uint32_t*)(ql + (g + 8) * 32 + u * 16 + 2 * j);
        aQl[u][2] = *(const uint32_t*)(ql + g * 32 + u * 16 + 8 + 2 * j);
        aQl[u][3] = *(const uint32_t*)(ql + (g + 8) * 32 + u * 16 + 8 + 2 * j);
    }

    float oacc[4][4];
#pragma unroll
    for (int nt = 0; nt < 4; nt++)
#pragma unroll
        for (int r = 0; r < 4; r++) oacc[nt][r] = 0.f;
    float lg = 0.f, lg8 = 0.f;

    const float* bp = bias_pair + h * 65536;

    for (int c = 0; c < 8; c++) {
        const int kc = c * 32;

        float2 bpf0[4], bpf1[4];
#pragma unroll
        for (int t = 0; t < 4; t++) {
            const int col = kc + 8 * t + 2 * j;
            bpf0[t] = *(const float2*)(bp + (q0w + g) * 256 + col);
            bpf1[t] = *(const float2*)(bp + (q0w + g + 8) * 256 + col);
        }

        float d[4][4];
#pragma unroll
        for (int t = 0; t < 4; t++)
#pragma unroll
            for (int r = 0; r < 4; r++) d[t][r] = 0.f;
#pragma unroll
        for (int u = 0; u < 2; u++) {
#pragma unroll
            for (int t = 0; t < 4; t++) {
                const int kr = (kc + 8 * t + g) * 20;
                uint32_t bh[2] = {Khi[kr + 8 * u + j], Khi[kr + 8 * u + j + 4]};
                uint32_t bl[2] = {Klo[kr + 8 * u + j], Klo[kr + 8 * u + j + 4]};
                mma_bf16(d[t], aQh[u], bh);
                mma_bf16(d[t], aQh[u], bl);
                mma_bf16(d[t], aQl[u], bh);
            }
        }

        float p[4][4];
#pragma unroll
        for (int t = 0; t < 4; t++) {
            const int col = kc + 8 * t + 2 * j;
            const float bm0 = bms[col], bm1 = bms[col + 1];
            p[t][0] = __expf(d[t][0] + bm0 + bpf0[t].x);
            p[t][1] = __expf(d[t][1] + bm1 + bpf0[t].y);
            p[t][2] = __expf(d[t][2] + bm0 + bpf1[t].x);
            p[t][3] = __expf(d[t][3] + bm1 + bpf1[t].y);
            lg  += p[t][0] + p[t][1];
            lg8 += p[t][2] + p[t][3];
        }

        uint32_t ah[2][4], al[2][4];
#pragma unroll
        for (int u2 = 0; u2 < 2; u2++) {
            split2(p[2 * u2][0],     p[2 * u2][1],     ah[u2][0], al[u2][0]);
            split2(p[2 * u2][2],     p[2 * u2][3],     ah[u2][1], al[u2][1]);
            split2(p[2 * u2 + 1][0], p[2 * u2 + 1][1], ah[u2][2], al[u2][2]);
            split2(p[2 * u2 + 1][2], p[2 * u2 + 1][3], ah[u2][3], al[u2][3]);
        }

#pragma unroll
        for (int u2 = 0; u2 < 2; u2++) {
            const int kw = c * 16 + u2 * 8;
#pragma unroll
            for (int nt = 0; nt < 4; nt++) {
                const int vr = (nt * 8 + g) * 132;
                uint32_t bvh[2] = {Vthi[vr + kw + j], Vthi[vr + kw + j + 4]};
                uint32_t bvl[2] = {Vtlo[vr + kw + j], Vtlo[vr + kw + j + 4]};
                mma_bf16(oacc[nt], ah[u2], bvh);
                mma_bf16(oacc[nt], ah[u2], bvl);
                mma_bf16(oacc[nt], al[u2], bvh);
            }
        }
    }

    lg  += __shfl_xor_sync(0xffffffff, lg, 1);
    lg  += __shfl_xor_sync(0xffffffff, lg, 2);
    lg8 += __shfl_xor_sync(0xffffffff, lg8, 1);
    lg8 += __shfl_xor_sync(0xffffffff, lg8, 2);
    const float il  = 1.f / lg;
    const float il8 = 1.f / lg8;

    const int r0 = s * 256 + q0w + g;
    const int r1 = r0 + 8;
#pragma unroll
    for (int nt = 0; nt < 4; nt++) {
        const int colb = h * 32 + nt * 8 + 2 * j;
        const float2 g0 = *(const float2*)(gbuf + r0 * 256 + colb);
        const float2 g1 = *(const float2*)(gbuf + r1 * 256 + colb);
        uint32_t hi, lo;
        split2h(oacc[nt][0] * il * g0.x, oacc[nt][1] * il * g0.y, hi, lo);
        *(uint32_t*)(obh + r0 * 256 + colb) = hi;
        *(uint32_t*)(obl + r0 * 256 + colb) = lo;
        split2h(oacc[nt][2] * il8 * g1.x, oacc[nt][3] * il8 * g1.y, hi, lo);
        *(uint32_t*)(obh + r1 * 256 + colb) = hi;
        *(uint32_t*)(obl + r1 * 256 + colb) = lo;
    }
}

// ---------------------------------------------------------------------------
// Launch: 4 kernels (conv, merged proj, attention, out-GEMM)
// ---------------------------------------------------------------------------
extern "C" void kernel_launch(void* const* d_in, const int* in_sizes, int n_in,
                              void* d_out, int out_size)
{
    const float* q_x   = (const float*)d_in[0];
    const float* kv_x  = (const float*)d_in[1];
    const float* bmask = (const float*)d_in[2];
    const float* bpair = (const float*)d_in[3];
    const float* Wq    = (const float*)d_in[4];
    const float* Wk    = (const float*)d_in[5];
    const float* Wv    = (const float*)d_in[6];
    const float* Wg    = (const float*)d_in[7];
    const float* bg    = (const float*)d_in[8];
    const float* Wo    = (const float*)d_in[9];
    const float* bo    = (const float*)d_in[10];
    float* out = (float*)d_out;

    auto getb = [](const void* sym) {
        void* p; cudaGetSymbolAddress(&p, sym); return (__nv_bfloat16*)p;
    };
    auto geth = [](const void* sym) {
        void* p; cudaGetSymbolAddress(&p, sym); return (__half*)p;
    };
    __nv_bfloat16 *qxh = getb(g_qxh4),  *qxl = getb(g_qxl4);
    __nv_bfloat16 *kvxh = getb(g_kvxh4), *kvxl = getb(g_kvxl4);
    __half *qxfh = geth(g_qxfh4), *qxfl = geth(g_qxfl4);
    __half *kvxfh = geth(g_kvxfh4), *kvxfl = geth(g_kvxfl4);
    __nv_bfloat16 *wqh = getb(g_wqh4), *wql = getb(g_wql4);
    __nv_bfloat16 *wkh = getb(g_wkh4), *wkl = getb(g_wkl4);
    __half *wvf = geth(g_wvf4), *wgf = geth(g_wgf4), *wof = geth(g_wof4);
    __nv_bfloat16 *qph = getb(g_qhi4), *qpl = getb(g_qlo4);
    __nv_bfloat16 *kph = getb(g_khi4), *kpl = getb(g_klo4);
    __nv_bfloat16 *vph = getb(g_vthi4), *vpl = getb(g_vtlo4);
    __half *obh = geth(g_obh4), *obl = geth(g_obl4);
    float* gbp;
    cudaGetSymbolAddress((void**)&gbp, g_gbuf);

    const int gsm = 81920;   // bf16 path: 2 x 40960
    cudaFuncSetAttribute(gemm_proj, cudaFuncAttributeMaxDynamicSharedMemorySize, gsm);
    cudaFuncSetAttribute(gemm_out,  cudaFuncAttributeMaxDynamicSharedMemorySize, gsm);
    cudaFuncSetAttribute(attn_mma,  cudaFuncAttributeMaxDynamicSharedMemorySize, 75776);

    ConvPtrs P = {};
    P.src[0] = q_x;  P.bh[0] = qxh;  P.bl[0] = qxl;  P.fh[0] = qxfh;  P.fl[0] = qxfl;
    P.src[1] = kv_x; P.bh[1] = kvxh; P.bl[1] = kvxl; P.fh[1] = kvxfh; P.fl[1] = kvxfl;
    P.src[2] = Wq;   P.bh[2] = wqh;  P.bl[2] = wql;
    P.src[3] = Wk;   P.bh[3] = wkh;  P.bl[3] = wkl;
    P.src[4] = Wv;   P.fs[4] = wvf;
    P.src[5] = Wg;   P.fs[5] = wgf;
    P.src[6] = Wo;   P.fs[6] = wof;
    conv_all<<<8352, 256>>>(P);

    gemm_proj<<<dim3(M_ROWS / 128, 2, 4), 256, gsm>>>(
        qxh, qxl, kvxh, kvxl, qxfh, qxfl, kvxfh, kvxfl,
        wqh, wql, wkh, wkl, wvf, wgf,
        bg, gbp, qph, qpl, kph, kpl, vph, vpl);

    attn_mma<<<dim3(S_DIM * H_DIM, 2), 256, 75776>>>(
        qph, qpl, kph, kpl, vph, vpl, gbp, bmask, bpair, obh, obl);

    gemm_out<<<dim3(M_ROWS / 128, 2), 256, 61440>>>(obh, obl, wof, bo, out);
}

// round 17
// speedup vs baseline: 1.1896x; 1.0581x over previous
#include <cuda_runtime.h>
#include <cuda_bf16.h>
#include <cuda_fp16.h>
#include <cstdint>

// ---------------------------------------------------------------------------
// Problem constants
// ---------------------------------------------------------------------------
#define S_DIM 128
#define Q_DIM 256
#define C_DIM 256
#define H_DIM 8
#define DH_DIM 32
#define M_ROWS (S_DIM * Q_DIM)        // 32768

// ---------------------------------------------------------------------------
// Scratch (static device globals). uint4 => 16B align.
// ---------------------------------------------------------------------------
#define XU4 (M_ROWS * 256 / 8)
#define WU4 (256 * 256 / 8)
__device__ uint4 g_qxh4[XU4],  g_qxl4[XU4];    // bf16 h/l q_x
__device__ uint4 g_kvxh4[XU4], g_kvxl4[XU4];   // bf16 h/l kv_x
__device__ uint4 g_qxfh4[XU4],  g_qxfl4[XU4];  // fp16 h/l q_x
__device__ uint4 g_kvxfh4[XU4], g_kvxfl4[XU4]; // fp16 h/l kv_x
__device__ uint4 g_wqh4[WU4], g_wql4[WU4];     // bf16 h/l Wq
__device__ uint4 g_wkh4[WU4], g_wkl4[WU4];     // bf16 h/l Wk
__device__ uint4 g_wvf4[WU4];                  // fp16 single Wv
__device__ uint4 g_wgf4[WU4];                  // fp16 single Wg
__device__ uint4 g_wof4[WU4];                  // fp16 single Wo
__device__ uint4 g_qhi4[XU4], g_qlo4[XU4];     // Q proj bf16 [s][h][q][dh]
__device__ uint4 g_khi4[XU4], g_klo4[XU4];     // K proj bf16 [s][h][q][dh]
__device__ uint4 g_vtf4[XU4];                  // V proj fp16 single [s][h][dh][k]
__device__ uint4 g_obh4[XU4], g_obl4[XU4];     // attn out fp16 h/l [m][tot]
__device__ float g_gbuf[M_ROWS * C_DIM];

// ---------------------------------------------------------------------------
// Helpers
// ---------------------------------------------------------------------------
__device__ __forceinline__ uint32_t smem_u32(const void* p) {
    uint32_t a;
    asm("{ .reg .u64 t; cvta.to.shared.u64 t, %1; cvt.u32.u64 %0, t; }"
        : "=r"(a) : "l"(p));
    return a;
}
__device__ __forceinline__ void cp16(uint32_t dst, const void* src) {
    asm volatile("cp.async.cg.shared.global [%0], [%1], 16;"
                 :: "r"(dst), "l"(src) : "memory");
}
__device__ __forceinline__ void cp_commit() {
    asm volatile("cp.async.commit_group;" ::: "memory");
}
template <int N>
__device__ __forceinline__ void cp_wait() {
    asm volatile("cp.async.wait_group %0;" :: "n"(N) : "memory");
}
__device__ __forceinline__ void ldsm_x4(uint32_t& r0, uint32_t& r1,
                                        uint32_t& r2, uint32_t& r3,
                                        uint32_t addr) {
    asm volatile("ldmatrix.sync.aligned.m8n8.x4.shared.b16 {%0,%1,%2,%3}, [%4];"
                 : "=r"(r0), "=r"(r1), "=r"(r2), "=r"(r3) : "r"(addr));
}
__device__ __forceinline__ void mma_bf16(float* d, const uint32_t* a,
                                         const uint32_t* b) {
    asm volatile(
        "mma.sync.aligned.m16n8k16.row.col.f32.bf16.bf16.f32 "
        "{%0,%1,%2,%3}, {%4,%5,%6,%7}, {%8,%9}, {%0,%1,%2,%3};"
        : "+f"(d[0]), "+f"(d[1]), "+f"(d[2]), "+f"(d[3])
        : "r"(a[0]), "r"(a[1]), "r"(a[2]), "r"(a[3]), "r"(b[0]), "r"(b[1]));
}
__device__ __forceinline__ void mma_f16(float* d, const uint32_t* a,
                                        const uint32_t* b) {
    asm volatile(
        "mma.sync.aligned.m16n8k16.row.col.f32.f16.f16.f32 "
        "{%0,%1,%2,%3}, {%4,%5,%6,%7}, {%8,%9}, {%0,%1,%2,%3};"
        : "+f"(d[0]), "+f"(d[1]), "+f"(d[2]), "+f"(d[3])
        : "r"(a[0]), "r"(a[1]), "r"(a[2]), "r"(a[3]), "r"(b[0]), "r"(b[1]));
}
__device__ __forceinline__ uint32_t pack_bf(__nv_bfloat16 e0, __nv_bfloat16 e1) {
    return ((uint32_t)__bfloat16_as_ushort(e1) << 16) |
           (uint32_t)__bfloat16_as_ushort(e0);
}
__device__ __forceinline__ void split2(float x0, float x1,
                                       uint32_t& hi, uint32_t& lo) {
    __nv_bfloat16 h0 = __float2bfloat16(x0);
    __nv_bfloat16 h1 = __float2bfloat16(x1);
    __nv_bfloat16 l0 = __float2bfloat16(x0 - __bfloat162float(h0));
    __nv_bfloat16 l1 = __float2bfloat16(x1 - __bfloat162float(h1));
    hi = pack_bf(h0, h1);
    lo = pack_bf(l0, l1);
}
__device__ __forceinline__ uint32_t pack_h(__half e0, __half e1) {
    return ((uint32_t)__half_as_ushort(e1) << 16) |
           (uint32_t)__half_as_ushort(e0);
}
__device__ __forceinline__ void split2h(float x0, float x1,
                                        uint32_t& hi, uint32_t& lo) {
    __half h0 = __float2half(x0);
    __half h1 = __float2half(x1);
    __half l0 = __float2half(x0 - __half2float(h0));
    __half l1 = __float2half(x1 - __half2float(h1));
    hi = pack_h(h0, h1);
    lo = pack_h(l0, l1);
}

// ---------------------------------------------------------------------------
// Merged converter. jb 0,1 (q_x,kv_x): bf16 h/l + fp16 h/l.
// jb 2,3 (Wq,Wk): bf16 h/l. jb 4,5,6 (Wv,Wg,Wo): fp16 single.
// ---------------------------------------------------------------------------
struct ConvPtrs {
    const float* src[7];
    __nv_bfloat16* bh[7];
    __nv_bfloat16* bl[7];
    __half* fh[7];
    __half* fl[7];
    __half* fs[7];
};
__global__ __launch_bounds__(256)
void conv_all(ConvPtrs P)
{
    int b = blockIdx.x, jb, off;
    if (b < 4096)      { jb = 0; off = b; }
    else if (b < 8192) { jb = 1; off = b - 4096; }
    else               { jb = 2 + ((b - 8192) >> 5); off = (b - 8192) & 31; }

    const int i = (off * 256 + threadIdx.x) * 8;
    float v[8];
    *(float4*)(v)     = *(const float4*)(P.src[jb] + i);
    *(float4*)(v + 4) = *(const float4*)(P.src[jb] + i + 4);

    if (jb < 4) {
        uint32_t h[4], l[4];
#pragma unroll
        for (int k = 0; k < 4; k++) split2(v[2*k], v[2*k+1], h[k], l[k]);
        *(uint4*)(P.bh[jb] + i) = make_uint4(h[0], h[1], h[2], h[3]);
        *(uint4*)(P.bl[jb] + i) = make_uint4(l[0], l[1], l[2], l[3]);
        if (jb < 2) {
#pragma unroll
            for (int k = 0; k < 4; k++) split2h(v[2*k], v[2*k+1], h[k], l[k]);
            *(uint4*)(P.fh[jb] + i) = make_uint4(h[0], h[1], h[2], h[3]);
            *(uint4*)(P.fl[jb] + i) = make_uint4(l[0], l[1], l[2], l[3]);
        }
    } else {
        uint32_t s[4];
#pragma unroll
        for (int k = 0; k < 4; k++)
            s[k] = pack_h(__float2half(v[2*k]), __float2half(v[2*k+1]));
        *(uint4*)(P.fs[jb] + i) = make_uint4(s[0], s[1], s[2], s[3]);
    }
}

// ---------------------------------------------------------------------------
// Shared GEMM context
// ---------------------------------------------------------------------------
struct GemmCtx {
    int tid, wid, lane, g, j, wm, wn, m0, n0, rowq, colq, srow, sp;
    uint32_t rowoff, dynb;
};
__device__ __forceinline__ GemmCtx make_ctx(uint32_t dynb) {
    GemmCtx C;
    C.tid  = threadIdx.x;
    C.wid  = C.tid >> 5;
    C.lane = C.tid & 31;
    C.g    = C.lane >> 2;
    C.j    = C.lane & 3;
    C.wm   = C.wid & 1;
    C.wn   = C.wid >> 1;
    C.m0   = blockIdx.x * 128;
    C.n0   = blockIdx.y * 128;
    C.rowq = ((C.lane >> 3) & 1) * 8 + (C.lane & 7);
    C.colq = (C.lane >> 4) * 4;
    C.srow = C.tid >> 1;
    C.sp   = (C.tid & 1) * 2;
    C.rowoff = (uint32_t)C.srow * 80 + (uint32_t)C.sp * 16;
    C.dynb = dynb;
    return C;
}

// ---------------------------------------------------------------------------
// bf16x3 mainloop (R12-exact): BK=32, 2-stage, single sync.
// ---------------------------------------------------------------------------
__device__ __forceinline__ void gemm_main(
    const GemmCtx& C, const __nv_bfloat16* __restrict__ Ah_g,
    const __nv_bfloat16* __restrict__ Al_g,
    const __nv_bfloat16* __restrict__ Bh_g,
    const __nv_bfloat16* __restrict__ Bl_g, float acc[4][4][4])
{
#pragma unroll
    for (int mt = 0; mt < 4; mt++)
#pragma unroll
        for (int nt = 0; nt < 4; nt++)
#pragma unroll
            for (int r = 0; r < 4; r++) acc[mt][nt][r] = 0.f;

#define STAGE(c, b)                                                            \
    do {                                                                       \
        const uint32_t bb = C.dynb + (b) * 40960;                              \
        const int co = (c) * 32 + C.sp * 8;                                    \
        cp16(bb + C.rowoff,              Ah_g + (C.m0 + C.srow) * 256 + co);   \
        cp16(bb + C.rowoff + 16,         Ah_g + (C.m0 + C.srow) * 256 + co + 8);\
        cp16(bb + 10240 + C.rowoff,      Al_g + (C.m0 + C.srow) * 256 + co);   \
        cp16(bb + 10240 + C.rowoff + 16, Al_g + (C.m0 + C.srow) * 256 + co + 8);\
        cp16(bb + 20480 + C.rowoff,      Bh_g + (C.n0 + C.srow) * 256 + co);   \
        cp16(bb + 20480 + C.rowoff + 16, Bh_g + (C.n0 + C.srow) * 256 + co + 8);\
        cp16(bb + 30720 + C.rowoff,      Bl_g + (C.n0 + C.srow) * 256 + co);   \
        cp16(bb + 30720 + C.rowoff + 16, Bl_g + (C.n0 + C.srow) * 256 + co + 8);\
        cp_commit();                                                           \
    } while (0)

    STAGE(0, 0);
    for (int c = 0; c < 8; c++) {
        const int b = c & 1;
        cp_wait<0>();
        __syncthreads();
        if (c < 7) STAGE(c + 1, b ^ 1);

        const uint32_t bufb = C.dynb + b * 40960;
#pragma unroll
        for (int kt = 0; kt < 2; kt++) {
            const uint32_t cb = (uint32_t)(kt * 8 + C.colq) * 4;
            uint32_t ah[4][4], al[4][4], bhp[2][4], blp[2][4];
#pragma unroll
            for (int mt = 0; mt < 4; mt++) {
                const uint32_t ra =
                    (uint32_t)(C.wm * 64 + mt * 16 + C.rowq) * 80 + cb;
                ldsm_x4(ah[mt][0], ah[mt][1], ah[mt][2], ah[mt][3], bufb + ra);
                ldsm_x4(al[mt][0], al[mt][1], al[mt][2], al[mt][3],
                        bufb + 10240 + ra);
            }
#pragma unroll
            for (int np = 0; np < 2; np++) {
                const uint32_t rb =
                    (uint32_t)(C.wn * 32 + np * 16 + C.rowq) * 80 + cb;
                ldsm_x4(bhp[np][0], bhp[np][1], bhp[np][2], bhp[np][3],
                        bufb + 20480 + rb);
                ldsm_x4(blp[np][0], blp[np][1], blp[np][2], blp[np][3],
                        bufb + 30720 + rb);
            }
#pragma unroll
            for (int mt = 0; mt < 4; mt++)
#pragma unroll
                for (int nt = 0; nt < 4; nt++) {
                    const int np = nt >> 1, sel = nt & 1;
                    uint32_t bh2[2] = {bhp[np][sel], bhp[np][sel + 2]};
                    uint32_t bl2[2] = {blp[np][sel], blp[np][sel + 2]};
                    mma_bf16(acc[mt][nt], ah[mt], bh2);
                    mma_bf16(acc[mt][nt], ah[mt], bl2);
                    mma_bf16(acc[mt][nt], al[mt], bh2);
                }
        }
    }
#undef STAGE
}

// ---------------------------------------------------------------------------
// fp16x2 mainloop: A split fp16 hi/lo, B single fp16.
// ---------------------------------------------------------------------------
__device__ __forceinline__ void gemm_main_f16(
    const GemmCtx& C, const __half* __restrict__ Ah_g,
    const __half* __restrict__ Al_g,
    const __half* __restrict__ Bs_g, float acc[4][4][4])
{
#pragma unroll
    for (int mt = 0; mt < 4; mt++)
#pragma unroll
        for (int nt = 0; nt < 4; nt++)
#pragma unroll
            for (int r = 0; r < 4; r++) acc[mt][nt][r] = 0.f;

#define STAGEH(c, b)                                                           \
    do {                                                                       \
        const uint32_t bb = C.dynb + (b) * 30720;                              \
        const int co = (c) * 32 + C.sp * 8;                                    \
        cp16(bb + C.rowoff,              Ah_g + (C.m0 + C.srow) * 256 + co);   \
        cp16(bb + C.rowoff + 16,         Ah_g + (C.m0 + C.srow) * 256 + co + 8);\
        cp16(bb + 10240 + C.rowoff,      Al_g + (C.m0 + C.srow) * 256 + co);   \
        cp16(bb + 10240 + C.rowoff + 16, Al_g + (C.m0 + C.srow) * 256 + co + 8);\
        cp16(bb + 20480 + C.rowoff,      Bs_g + (C.n0 + C.srow) * 256 + co);   \
        cp16(bb + 20480 + C.rowoff + 16, Bs_g + (C.n0 + C.srow) * 256 + co + 8);\
        cp_commit();                                                           \
    } while (0)

    STAGEH(0, 0);
    for (int c = 0; c < 8; c++) {
        const int b = c & 1;
        cp_wait<0>();
        __syncthreads();
        if (c < 7) STAGEH(c + 1, b ^ 1);

        const uint32_t bufb = C.dynb + b * 30720;
#pragma unroll
        for (int kt = 0; kt < 2; kt++) {
            const uint32_t cb = (uint32_t)(kt * 8 + C.colq) * 4;
            uint32_t ah[4][4], al[4][4], bp[2][4];
#pragma unroll
            for (int mt = 0; mt < 4; mt++) {
                const uint32_t ra =
                    (uint32_t)(C.wm * 64 + mt * 16 + C.rowq) * 80 + cb;
                ldsm_x4(ah[mt][0], ah[mt][1], ah[mt][2], ah[mt][3], bufb + ra);
                ldsm_x4(al[mt][0], al[mt][1], al[mt][2], al[mt][3],
                        bufb + 10240 + ra);
            }
#pragma unroll
            for (int np = 0; np < 2; np++) {
                const uint32_t rb =
                    (uint32_t)(C.wn * 32 + np * 16 + C.rowq) * 80 + cb;
                ldsm_x4(bp[np][0], bp[np][1], bp[np][2], bp[np][3],
                        bufb + 20480 + rb);
            }
#pragma unroll
            for (int mt = 0; mt < 4; mt++)
#pragma unroll
                for (int nt = 0; nt < 4; nt++) {
                    const int np = nt >> 1, sel = nt & 1;
                    uint32_t b2[2] = {bp[np][sel], bp[np][sel + 2]};
                    mma_f16(acc[mt][nt], ah[mt], b2);
                    mma_f16(acc[mt][nt], al[mt], b2);
                }
        }
    }
#undef STAGEH
}

// ---------------------------------------------------------------------------
// Merged projection GEMM: grid (256, 2, 4).
// z=0 Q (bf16x3), z=1 K (bf16x3), z=2 V (fp16x2, fp16-single transposed out),
// z=3 gate (fp16x2, sigmoid fp32 out).
// ---------------------------------------------------------------------------
__global__ __launch_bounds__(256)
void gemm_proj(const __nv_bfloat16* __restrict__ qxh,
               const __nv_bfloat16* __restrict__ qxl,
               const __nv_bfloat16* __restrict__ kvxh,
               const __nv_bfloat16* __restrict__ kvxl,
               const __half* __restrict__ qxfh, const __half* __restrict__ qxfl,
               const __half* __restrict__ kvxfh, const __half* __restrict__ kvxfl,
               const __nv_bfloat16* __restrict__ wqh,
               const __nv_bfloat16* __restrict__ wql,
               const __nv_bfloat16* __restrict__ wkh,
               const __nv_bfloat16* __restrict__ wkl,
               const __half* __restrict__ wvf, const __half* __restrict__ wgf,
               const float* __restrict__ bg, float* __restrict__ gbuf,
               __nv_bfloat16* __restrict__ qph, __nv_bfloat16* __restrict__ qpl,
               __nv_bfloat16* __restrict__ kph, __nv_bfloat16* __restrict__ kpl,
               __half* __restrict__ vtf)
{
    extern __shared__ uint32_t dyn[];
    const int z = blockIdx.z;
    GemmCtx C = make_ctx(smem_u32(dyn));
    float acc[4][4][4];

    if (z == 0)      gemm_main(C, qxh, qxl, wqh, wql, acc);
    else if (z == 1) gemm_main(C, kvxh, kvxl, wkh, wkl, acc);
    else if (z == 2) gemm_main_f16(C, kvxfh, kvxfl, wvf, acc);
    else             gemm_main_f16(C, qxfh, qxfl, wgf, acc);

    __nv_bfloat16* outh = (z == 0) ? qph : kph;
    __nv_bfloat16* outl = (z == 0) ? qpl : kpl;

    const int mbase = C.m0 + C.wm * 64;
#pragma unroll
    for (int mt = 0; mt < 4; mt++) {
#pragma unroll
        for (int nt = 0; nt < 4; nt++) {
            const int n = C.n0 + C.wn * 32 + nt * 8 + 2 * C.j;
#pragma unroll
            for (int half = 0; half < 2; half++) {
                const int m = mbase + mt * 16 + C.g + half * 8;
                float2 v = make_float2(acc[mt][nt][half * 2],
                                       acc[mt][nt][half * 2 + 1]);
                const int s = m >> 8, q = m & 255;
                const int h = n >> 5, dh = n & 31;
                if (z < 2) {                 // Q/K: bf16 split [s][h][q][dh]
                    const int idx = (((s << 3) + h) * 256 + q) * 32 + dh;
                    uint32_t hi, lo;
                    split2(v.x, v.y, hi, lo);
                    *(uint32_t*)(outh + idx) = hi;
                    *(uint32_t*)(outl + idx) = lo;
                } else if (z == 2) {         // V: fp16 single transposed
                    const int i0 = (((s << 3) + h) * 32 + dh) * 256 + q;
                    vtf[i0]       = __float2half(v.x);
                    vtf[i0 + 256] = __float2half(v.y);
                } else {                     // gate: sigmoid fp32
                    const float2 bb = *(const float2*)(bg + n);
                    v.x = 1.f / (1.f + __expf(-(v.x + bb.x)));
                    v.y = 1.f / (1.f + __expf(-(v.y + bb.y)));
                    *(float2*)(gbuf + m * 256 + n) = v;
                }
            }
        }
    }
}

// ---------------------------------------------------------------------------
// Output GEMM (fp16x2): out = O * Wo^T + bo
// ---------------------------------------------------------------------------
__global__ __launch_bounds__(256)
void gemm_out(const __half* __restrict__ Ah_g, const __half* __restrict__ Al_g,
              const __half* __restrict__ Bs_g,
              const float* __restrict__ bias, float* __restrict__ outf)
{
    extern __shared__ uint32_t dyn[];
    GemmCtx C = make_ctx(smem_u32(dyn));
    float acc[4][4][4];
    gemm_main_f16(C, Ah_g, Al_g, Bs_g, acc);

    const int mbase = C.m0 + C.wm * 64;
#pragma unroll
    for (int mt = 0; mt < 4; mt++) {
#pragma unroll
        for (int nt = 0; nt < 4; nt++) {
            const int n = C.n0 + C.wn * 32 + nt * 8 + 2 * C.j;
            const float2 bb = *(const float2*)(bias + n);
#pragma unroll
            for (int half = 0; half < 2; half++) {
                const int m = mbase + mt * 16 + C.g + half * 8;
                float2 v = make_float2(acc[mt][nt][half * 2] + bb.x,
                                       acc[mt][nt][half * 2 + 1] + bb.y);
                *(float2*)(outf + m * 256 + n) = v;
            }
        }
    }
}

// ---------------------------------------------------------------------------
// MMA attention with flash-style online max.
// QK bf16x3 (validated); softmax per-row running max (P in (0,1]);
// PV single fp16 P x single fp16 V: 1 MMA per tile (was 3).
// Smem: Khi[5120] Klo[5120] Vt[4224] bms[256] = 58880 B.
// ---------------------------------------------------------------------------
__global__ __launch_bounds__(256)
void attn_mma(const __nv_bfloat16* __restrict__ qh_g,
              const __nv_bfloat16* __restrict__ ql_g,
              const __nv_bfloat16* __restrict__ kh_g,
              const __nv_bfloat16* __restrict__ kl_g,
              const __half* __restrict__ vtf_g,
              const float* __restrict__ gbuf,
              const float* __restrict__ bias_mask,
              const float* __restrict__ bias_pair,
              __half* __restrict__ obh, __half* __restrict__ obl)
{
    extern __shared__ uint32_t smem[];
    uint32_t* Khi = smem;
    uint32_t* Klo = smem + 5120;
    uint32_t* Vt  = smem + 10240;
    float*    bms = (float*)(smem + 14464);

    const int tid  = threadIdx.x;
    const int wid  = tid >> 5;
    const int lane = tid & 31;
    const int g    = lane >> 2;
    const int j    = lane & 3;
    const int sh   = blockIdx.x;
    const int s    = sh >> 3;
    const int h    = sh & 7;
    const int q0w  = blockIdx.y * 128 + wid * 16;

    {
        const __nv_bfloat16* ksh = kh_g + sh * 256 * 32;
        const __nv_bfloat16* ksl = kl_g + sh * 256 * 32;
        const __half* vs = vtf_g + sh * 32 * 256;
        const uint32_t khb = smem_u32(Khi), klb = smem_u32(Klo);
        const uint32_t vtb = smem_u32(Vt);
#pragma unroll
        for (int it = 0; it < 4; it++) {
            const int ic  = it * 256 + tid;
            const int key = ic >> 2, part = ic & 3;
            cp16(khb + key * 80 + part * 16, ksh + key * 32 + part * 8);
            cp16(klb + key * 80 + part * 16, ksl + key * 32 + part * 8);
            const int d = ic >> 5, p5 = ic & 31;
            cp16(vtb + d * 528 + p5 * 16, vs + d * 256 + p5 * 8);
        }
        cp_commit();
        bms[tid] = bias_mask[s * 256 + tid];
        cp_wait<0>();
    }
    __syncthreads();

    const __nv_bfloat16* qh = qh_g + (sh * 256 + q0w) * 32;
    const __nv_bfloat16* ql = ql_g + (sh * 256 + q0w) * 32;
    uint32_t aQh[2][4], aQl[2][4];
#pragma unroll
    for (int u = 0; u < 2; u++) {
        aQh[u][0] = *(const uint32_t*)(qh + g * 32 + u * 16 + 2 * j);
        aQh[u][1] = *(const uint32_t*)(qh + (g + 8) * 32 + u * 16 + 2 * j);
        aQh[u][2] = *(const uint32_t*)(qh + g * 32 + u * 16 + 8 + 2 * j);
        aQh[u][3] = *(const uint32_t*)(qh + (g + 8) * 32 + u * 16 + 8 + 2 * j);
        aQl[u][0] = *(const uint32_t*)(ql + g * 32 + u * 16 + 2 * j);
        aQl[u][1] = *(const uint32_t*)(ql + (g + 8) * 32 + u * 16 + 2 * j);
        aQl[u][2] = *(const uint32_t*)(ql + g * 32 + u * 16 + 8 + 2 * j);
        aQl[u][3] = *(const uint32_t*)(ql + (g + 8) * 32 + u * 16 + 8 + 2 * j);
    }

    float oacc[4][4];
#pragma unroll
    for (int nt = 0; nt < 4; nt++)
#pragma unroll
        for (int r = 0; r < 4; r++) oacc[nt][r] = 0.f;
    float lg = 0.f, lg8 = 0.f;
    float m0 = -1e30f, m8 = -1e30f;

    const float* bp = bias_pair + h * 65536;

    for (int c = 0; c < 8; c++) {
        const int kc = c * 32;

        float2 bpf0[4], bpf1[4];
#pragma unroll
        for (int t = 0; t < 4; t++) {
            const int col = kc + 8 * t + 2 * j;
            bpf0[t] = *(const float2*)(bp + (q0w + g) * 256 + col);
            bpf1[t] = *(const float2*)(bp + (q0w + g + 8) * 256 + col);
        }

        // ---- QK: bf16x3, 4 independent accumulators ----------------------
        float d[4][4];
#pragma unroll
        for (int t = 0; t < 4; t++)
#pragma unroll
            for (int r = 0; r < 4; r++) d[t][r] = 0.f;
#pragma unroll
        for (int u = 0; u < 2; u++) {
#pragma unroll
            for (int t = 0; t < 4; t++) {
                const int kr = (kc + 8 * t + g) * 20;
                uint32_t bh[2] = {Khi[kr + 8 * u + j], Khi[kr + 8 * u + j + 4]};
                uint32_t bl[2] = {Klo[kr + 8 * u + j], Klo[kr + 8 * u + j + 4]};
                mma_bf16(d[t], aQh[u], bh);
                mma_bf16(d[t], aQh[u], bl);
                mma_bf16(d[t], aQl[u], bh);
            }
        }

        // ---- scores + chunk row-max --------------------------------------
        float sc[4][4];
        float cm0 = -1e30f, cm8 = -1e30f;
#pragma unroll
        for (int t = 0; t < 4; t++) {
            const int col = kc + 8 * t + 2 * j;
            const float bm0v = bms[col], bm1v = bms[col + 1];
            sc[t][0] = d[t][0] + bm0v + bpf0[t].x;
            sc[t][1] = d[t][1] + bm1v + bpf0[t].y;
            sc[t][2] = d[t][2] + bm0v + bpf1[t].x;
            sc[t][3] = d[t][3] + bm1v + bpf1[t].y;
            cm0 = fmaxf(cm0, fmaxf(sc[t][0], sc[t][1]));
            cm8 = fmaxf(cm8, fmaxf(sc[t][2], sc[t][3]));
        }
        cm0 = fmaxf(cm0, __shfl_xor_sync(0xffffffff, cm0, 1));
        cm0 = fmaxf(cm0, __shfl_xor_sync(0xffffffff, cm0, 2));
        cm8 = fmaxf(cm8, __shfl_xor_sync(0xffffffff, cm8, 1));
        cm8 = fmaxf(cm8, __shfl_xor_sync(0xffffffff, cm8, 2));

        const float m0n = fmaxf(m0, cm0);
        const float m8n = fmaxf(m8, cm8);
        const float r0s = __expf(m0 - m0n);
        const float r8s = __expf(m8 - m8n);
        m0 = m0n;
        m8 = m8n;
        lg  *= r0s;
        lg8 *= r8s;
#pragma unroll
        for (int nt = 0; nt < 4; nt++) {
            oacc[nt][0] *= r0s; oacc[nt][1] *= r0s;
            oacc[nt][2] *= r8s; oacc[nt][3] *= r8s;
        }

        // ---- exp (P in (0,1]) + fp16 pack --------------------------------
        float p[4][4];
#pragma unroll
        for (int t = 0; t < 4; t++) {
            p[t][0] = __expf(sc[t][0] - m0);
            p[t][1] = __expf(sc[t][1] - m0);
            p[t][2] = __expf(sc[t][2] - m8);
            p[t][3] = __expf(sc[t][3] - m8);
            lg  += p[t][0] + p[t][1];
            lg8 += p[t][2] + p[t][3];
        }
        uint32_t ap[2][4];
#pragma unroll
        for (int u2 = 0; u2 < 2; u2++) {
            ap[u2][0] = pack_h(__float2half(p[2*u2][0]),   __float2half(p[2*u2][1]));
            ap[u2][1] = pack_h(__float2half(p[2*u2][2]),   __float2half(p[2*u2][3]));
            ap[u2][2] = pack_h(__float2half(p[2*u2+1][0]), __float2half(p[2*u2+1][1]));
            ap[u2][3] = pack_h(__float2half(p[2*u2+1][2]), __float2half(p[2*u2+1][3]));
        }

        // ---- PV: single fp16 MMA per tile --------------------------------
#pragma unroll
        for (int u2 = 0; u2 < 2; u2++) {
            const int kw = c * 16 + u2 * 8;
#pragma unroll
            for (int nt = 0; nt < 4; nt++) {
                const int vr = (nt * 8 + g) * 132;
                uint32_t bv[2] = {Vt[vr + kw + j], Vt[vr + kw + j + 4]};
                mma_f16(oacc[nt], ap[u2], bv);
            }
        }
    }

    lg  += __shfl_xor_sync(0xffffffff, lg, 1);
    lg  += __shfl_xor_sync(0xffffffff, lg, 2);
    lg8 += __shfl_xor_sync(0xffffffff, lg8, 1);
    lg8 += __shfl_xor_sync(0xffffffff, lg8, 2);
    const float il  = 1.f / lg;
    const float il8 = 1.f / lg8;

    const int r0 = s * 256 + q0w + g;
    const int r1 = r0 + 8;
#pragma unroll
    for (int nt = 0; nt < 4; nt++) {
        const int colb = h * 32 + nt * 8 + 2 * j;
        const float2 g0 = *(const float2*)(gbuf + r0 * 256 + colb);
        const float2 g1 = *(const float2*)(gbuf + r1 * 256 + colb);
        uint32_t hi, lo;
        split2h(oacc[nt][0] * il * g0.x, oacc[nt][1] * il * g0.y, hi, lo);
        *(uint32_t*)(obh + r0 * 256 + colb) = hi;
        *(uint32_t*)(obl + r0 * 256 + colb) = lo;
        split2h(oacc[nt][2] * il8 * g1.x, oacc[nt][3] * il8 * g1.y, hi, lo);
        *(uint32_t*)(obh + r1 * 256 + colb) = hi;
        *(uint32_t*)(obl + r1 * 256 + colb) = lo;
    }
}

// ---------------------------------------------------------------------------
// Launch: 4 kernels (conv, merged proj, attention, out-GEMM)
// ---------------------------------------------------------------------------
extern "C" void kernel_launch(void* const* d_in, const int* in_sizes, int n_in,
                              void* d_out, int out_size)
{
    const float* q_x   = (const float*)d_in[0];
    const float* kv_x  = (const float*)d_in[1];
    const float* bmask = (const float*)d_in[2];
    const float* bpair = (const float*)d_in[3];
    const float* Wq    = (const float*)d_in[4];
    const float* Wk    = (const float*)d_in[5];
    const float* Wv    = (const float*)d_in[6];
    const float* Wg    = (const float*)d_in[7];
    const float* bg    = (const float*)d_in[8];
    const float* Wo    = (const float*)d_in[9];
    const float* bo    = (const float*)d_in[10];
    float* out = (float*)d_out;

    auto getb = [](const void* sym) {
        void* p; cudaGetSymbolAddress(&p, sym); return (__nv_bfloat16*)p;
    };
    auto geth = [](const void* sym) {
        void* p; cudaGetSymbolAddress(&p, sym); return (__half*)p;
    };
    __nv_bfloat16 *qxh = getb(g_qxh4),  *qxl = getb(g_qxl4);
    __nv_bfloat16 *kvxh = getb(g_kvxh4), *kvxl = getb(g_kvxl4);
    __half *qxfh = geth(g_qxfh4), *qxfl = geth(g_qxfl4);
    __half *kvxfh = geth(g_kvxfh4), *kvxfl = geth(g_kvxfl4);
    __nv_bfloat16 *wqh = getb(g_wqh4), *wql = getb(g_wql4);
    __nv_bfloat16 *wkh = getb(g_wkh4), *wkl = getb(g_wkl4);
    __half *wvf = geth(g_wvf4), *wgf = geth(g_wgf4), *wof = geth(g_wof4);
    __nv_bfloat16 *qph = getb(g_qhi4), *qpl = getb(g_qlo4);
    __nv_bfloat16 *kph = getb(g_khi4), *kpl = getb(g_klo4);
    __half *vtf = geth(g_vtf4);
    __half *obh = geth(g_obh4), *obl = geth(g_obl4);
    float* gbp;
    cudaGetSymbolAddress((void**)&gbp, g_gbuf);

    const int gsm = 81920;
    cudaFuncSetAttribute(gemm_proj, cudaFuncAttributeMaxDynamicSharedMemorySize, gsm);
    cudaFuncSetAttribute(gemm_out,  cudaFuncAttributeMaxDynamicSharedMemorySize, gsm);
    cudaFuncSetAttribute(attn_mma,  cudaFuncAttributeMaxDynamicSharedMemorySize, 58880);

    ConvPtrs P = {};
    P.src[0] = q_x;  P.bh[0] = qxh;  P.bl[0] = qxl;  P.fh[0] = qxfh;  P.fl[0] = qxfl;
    P.src[1] = kv_x; P.bh[1] = kvxh; P.bl[1] = kvxl; P.fh[1] = kvxfh; P.fl[1] = kvxfl;
    P.src[2] = Wq;   P.bh[2] = wqh;  P.bl[2] = wql;
    P.src[3] = Wk;   P.bh[3] = wkh;  P.bl[3] = wkl;
    P.src[4] = Wv;   P.fs[4] = wvf;
    P.src[5] = Wg;   P.fs[5] = wgf;
    P.src[6] = Wo;   P.fs[6] = wof;
    conv_all<<<8352, 256>>>(P);

    gemm_proj<<<dim3(M_ROWS / 128, 2, 4), 256, gsm>>>(
        qxh, qxl, kvxh, kvxl, qxfh, qxfl, kvxfh, kvxfl,
        wqh, wql, wkh, wkl, wvf, wgf,
        bg, gbp, qph, qpl, kph, kpl, vtf);

    attn_mma<<<dim3(S_DIM * H_DIM, 2), 256, 58880>>>(
        qph, qpl, kph, kpl, vtf, gbp, bmask, bpair, obh, obl);

    gemm_out<<<dim3(M_ROWS / 128, 2), 256, 61440>>>(obh, obl, wof, bo, out);
}